// round 9
// baseline (speedup 1.0000x reference)
#include <cuda_runtime.h>

// Problem constants (from reference): WIDTH=1024, HALF=512, DEPTH=32, BATCH=32768.
// Row layout: 1024 floats = 256 float4; x0 = slots [0,128), x1 = slots [128,256).
// Math: each depth step applies [[1-w,w],[w,1-w]] = (1-w)I + wJ to pair (j, j+512).
// All steps for a given j commute; in the (s,d)=(x0+x1, x0-x1) eigenbasis the 32-step
// product has eigenvalue 1 on s and p_j = prod_i(1-2*w_ij) on d:
//   out0 = 0.5*s + (0.5*p_j)*d ;  out1 = 0.5*s - (0.5*p_j)*d
//
// R9 vs R8 (36.3us @ DRAM 74.7%): 2 rows per thread -> 4 independent LDG.128 in
// flight per thread (MLP 2 -> 4), 4096 blocks (half the prologues / barriers /
// wave transitions). Coalescing unchanged: warp = 8 slots x 4 rows = 4 full 128B
// lines per access.

#define GROUPS_PER_ROW 16   // 128 float4 slots / 8 slots per group
#define SLOTS_PER_GRP  8    // 8 float4 slots = 32 pairs per group
#define ROWS_PER_CHUNK 128  // 64 threads' rows x 2 rows per thread
#define ROW_STRIDE     64   // second row = first row + 64
#define BLOCK_THREADS  512

__global__ void __launch_bounds__(BLOCK_THREADS, 4)
butterfly_fused_kernel(const float* __restrict__ X, const float* __restrict__ params,
                       float* __restrict__ out, int n_rows) {
    __shared__ float shp[32];   // 0.5 * p_j for this block's 32 pair indices

    const int tid   = threadIdx.x;                         // 0..511
    const int group = blockIdx.x & (GROUPS_PER_ROW - 1);   // slot group 0..15
    const int chunk = blockIdx.x >> 4;                     // row chunk 0..255

    // ---- Addressing: warp = 8 consecutive slots x 4 consecutive rows ----
    const int s_in  = tid & (SLOTS_PER_GRP - 1);           // slot within group, 0..7
    const int r_in  = tid >> 3;                            // row within chunk, 0..63
    const int rowA  = chunk * ROWS_PER_CHUNK + r_in;
    const int rowB  = rowA + ROW_STRIDE;
    const bool actA = (rowA < n_rows);
    const bool actB = (rowB < n_rows);
    const int slot  = group * SLOTS_PER_GRP + s_in;        // 0..127

    const float4* a0p = reinterpret_cast<const float4*>(X + (size_t)rowA * 1024) + slot;
    const float4* a1p = reinterpret_cast<const float4*>(X + (size_t)rowA * 1024 + 512) + slot;
    const float4* b0p = reinterpret_cast<const float4*>(X + (size_t)rowB * 1024) + slot;
    const float4* b1p = reinterpret_cast<const float4*>(X + (size_t)rowB * 1024 + 512) + slot;

    // Issue all 4 independent streaming loads first (MLP=4); the params prologue
    // below hides entirely under their latency.
    float4 a0, a1, b0, b1;
    if (actA) { a0 = __ldcs(a0p); a1 = __ldcs(a1p); }
    if (actB) { b0 = __ldcs(b0p); b1 = __ldcs(b1p); }

    // ---- Prologue: cooperative p for pairs [group*32, group*32+32) ----
    // params slice = rows [group*32, group*32+32) = float4s [group*256, group*256+256).
    // First 256 threads each load one float4 (fully coalesced 4KB, L2-resident since
    // only 16 distinct slices exist chip-wide).
    if (tid < 256) {
        float4 w = __ldg(reinterpret_cast<const float4*>(params) + group * 256 + tid);
        float q = fmaf(-2.0f, w.x, 1.0f) * fmaf(-2.0f, w.y, 1.0f)
                * fmaf(-2.0f, w.z, 1.0f) * fmaf(-2.0f, w.w, 1.0f);
        // Each params row (32 floats) = 8 consecutive threads; product-reduce within
        // the 8-thread segment (segments never cross a warp since 8 | 32).
        q *= __shfl_xor_sync(0xFFFFFFFF, q, 1);
        q *= __shfl_xor_sync(0xFFFFFFFF, q, 2);
        q *= __shfl_xor_sync(0xFFFFFFFF, q, 4);
        if ((tid & 7) == 0) shp[tid >> 3] = 0.5f * q;      // local pair index 0..31
    }
    __syncthreads();

    // 4 half-p values for this slot: LDS.128 broadcast across threads sharing s_in.
    const float4 hp = reinterpret_cast<const float4*>(shp)[s_in];

    if (actA) {
        float4 o0, o1; float hs, t;
        hs = 0.5f * (a0.x + a1.x); t = hp.x * (a0.x - a1.x); o0.x = hs + t; o1.x = hs - t;
        hs = 0.5f * (a0.y + a1.y); t = hp.y * (a0.y - a1.y); o0.y = hs + t; o1.y = hs - t;
        hs = 0.5f * (a0.z + a1.z); t = hp.z * (a0.z - a1.z); o0.z = hs + t; o1.z = hs - t;
        hs = 0.5f * (a0.w + a1.w); t = hp.w * (a0.w - a1.w); o0.w = hs + t; o1.w = hs - t;
        __stcs(reinterpret_cast<float4*>(out + (size_t)rowA * 1024) + slot, o0);
        __stcs(reinterpret_cast<float4*>(out + (size_t)rowA * 1024 + 512) + slot, o1);
    }
    if (actB) {
        float4 o0, o1; float hs, t;
        hs = 0.5f * (b0.x + b1.x); t = hp.x * (b0.x - b1.x); o0.x = hs + t; o1.x = hs - t;
        hs = 0.5f * (b0.y + b1.y); t = hp.y * (b0.y - b1.y); o0.y = hs + t; o1.y = hs - t;
        hs = 0.5f * (b0.z + b1.z); t = hp.z * (b0.z - b1.z); o0.z = hs + t; o1.z = hs - t;
        hs = 0.5f * (b0.w + b1.w); t = hp.w * (b0.w - b1.w); o0.w = hs + t; o1.w = hs - t;
        __stcs(reinterpret_cast<float4*>(out + (size_t)rowB * 1024) + slot, o0);
        __stcs(reinterpret_cast<float4*>(out + (size_t)rowB * 1024 + 512) + slot, o1);
    }
}

extern "C" void kernel_launch(void* const* d_in, const int* in_sizes, int n_in,
                              void* d_out, int out_size) {
    const float* X      = (const float*)d_in[0];   // [32768, 1024] fp32
    const float* params = (const float*)d_in[1];   // [512, 32] fp32
    float* out          = (float*)d_out;           // [32768, 1024] fp32

    const int n_rows = out_size / 1024;            // 32768
    const int chunks = (n_rows + ROWS_PER_CHUNK - 1) / ROWS_PER_CHUNK;
    butterfly_fused_kernel<<<GROUPS_PER_ROW * chunks, BLOCK_THREADS>>>(X, params, out, n_rows);
}

// round 10
// speedup vs baseline: 1.0251x; 1.0251x over previous
#include <cuda_runtime.h>

// Problem constants (from reference): WIDTH=1024, HALF=512, DEPTH=32, BATCH=32768.
// Row layout: 1024 floats = 256 float4; x0 = slots [0,128), x1 = slots [128,256).
// Math: each depth step applies [[1-w,w],[w,1-w]] = (1-w)I + wJ to pair (j, j+512).
// All steps for a given j commute; in the (s,d)=(x0+x1, x0-x1) eigenbasis the 32-step
// product has eigenvalue 1 on s and p_j = prod_i(1-2*w_ij) on d:
//   out0 = 0.5*s + (0.5*p_j)*d ;  out1 = 0.5*s - (0.5*p_j)*d
//
// Final form (= R8, the best-measured config). Roofline evidence: three different
// structures (separate apply, fused 1-row, fused 2-row MLP=4) all measure
// 35.8-36.3us at 74-76% DRAM (~5.9-6.0 TB/s) -> DRAM R/W-turnaround bound, not
// MLP/issue/occupancy bound. Traffic (128MB+128MB, touch-once) is irreducible.

#define GROUPS_PER_ROW 16   // 128 float4 slots / 8 slots per group
#define SLOTS_PER_GRP  8    // 8 float4 slots = 32 pairs per group
#define ROWS_PER_CHUNK 64
#define BLOCK_THREADS  512

__global__ void __launch_bounds__(BLOCK_THREADS, 4)
butterfly_fused_kernel(const float* __restrict__ X, const float* __restrict__ params,
                       float* __restrict__ out, int n_rows) {
    __shared__ float shp[32];   // 0.5 * p_j for this block's 32 pair indices

    const int tid   = threadIdx.x;                         // 0..511
    const int group = blockIdx.x & (GROUPS_PER_ROW - 1);   // slot group 0..15
    const int chunk = blockIdx.x >> 4;                     // row chunk

    // ---- Addressing: warp = 8 consecutive slots x 4 consecutive rows ----
    // Every 32-lane access touches exactly 4 full 128B lines (fully coalesced).
    const int s_in = tid & (SLOTS_PER_GRP - 1);            // slot within group, 0..7
    const int r_in = tid >> 3;                             // row within chunk, 0..63
    const int row  = chunk * ROWS_PER_CHUNK + r_in;
    const bool active = (row < n_rows);
    const int slot = group * SLOTS_PER_GRP + s_in;         // 0..127

    const float4* x0p = reinterpret_cast<const float4*>(X   + (size_t)row * 1024) + slot;
    const float4* x1p = reinterpret_cast<const float4*>(X   + (size_t)row * 1024 + 512) + slot;
    float4*       o0p = reinterpret_cast<float4*>(out + (size_t)row * 1024) + slot;
    float4*       o1p = reinterpret_cast<float4*>(out + (size_t)row * 1024 + 512) + slot;

    // Issue the streaming loads FIRST; the params prologue hides under their latency.
    float4 x0, x1;
    if (active) {
        x0 = __ldcs(x0p);   // touch-once data: evict-first
        x1 = __ldcs(x1p);
    }

    // ---- Prologue: cooperative p for pairs [group*32, group*32+32) ----
    // params slice = rows [group*32, group*32+32) = float4s [group*256, group*256+256).
    // First 256 threads each load one float4 (coalesced 4KB; only 16 distinct slices
    // chip-wide -> L2-resident after first wave).
    if (tid < 256) {
        float4 w = __ldg(reinterpret_cast<const float4*>(params) + group * 256 + tid);
        float q = fmaf(-2.0f, w.x, 1.0f) * fmaf(-2.0f, w.y, 1.0f)
                * fmaf(-2.0f, w.z, 1.0f) * fmaf(-2.0f, w.w, 1.0f);
        // Each params row (32 floats) = 8 consecutive threads; product-reduce within
        // the 8-thread segment (segments never cross a warp since 8 | 32).
        q *= __shfl_xor_sync(0xFFFFFFFF, q, 1);
        q *= __shfl_xor_sync(0xFFFFFFFF, q, 2);
        q *= __shfl_xor_sync(0xFFFFFFFF, q, 4);
        if ((tid & 7) == 0) shp[tid >> 3] = 0.5f * q;      // local pair index 0..31
    }
    __syncthreads();

    if (!active) return;

    // 4 half-p values for this slot: LDS.128, conflict-free; threads sharing s_in
    // broadcast the same 16B.
    float4 hp = reinterpret_cast<const float4*>(shp)[s_in];

    float4 o0, o1;
    {
        float hs, t;
        hs = 0.5f * (x0.x + x1.x); t = hp.x * (x0.x - x1.x); o0.x = hs + t; o1.x = hs - t;
        hs = 0.5f * (x0.y + x1.y); t = hp.y * (x0.y - x1.y); o0.y = hs + t; o1.y = hs - t;
        hs = 0.5f * (x0.z + x1.z); t = hp.z * (x0.z - x1.z); o0.z = hs + t; o1.z = hs - t;
        hs = 0.5f * (x0.w + x1.w); t = hp.w * (x0.w - x1.w); o0.w = hs + t; o1.w = hs - t;
    }

    __stcs(o0p, o0);
    __stcs(o1p, o1);
}

extern "C" void kernel_launch(void* const* d_in, const int* in_sizes, int n_in,
                              void* d_out, int out_size) {
    const float* X      = (const float*)d_in[0];   // [32768, 1024] fp32
    const float* params = (const float*)d_in[1];   // [512, 32] fp32
    float* out          = (float*)d_out;           // [32768, 1024] fp32

    const int n_rows = out_size / 1024;            // 32768
    const int chunks = (n_rows + ROWS_PER_CHUNK - 1) / ROWS_PER_CHUNK;
    butterfly_fused_kernel<<<GROUPS_PER_ROW * chunks, BLOCK_THREADS>>>(X, params, out, n_rows);
}